// round 1
// baseline (speedup 1.0000x reference)
#include <cuda_runtime.h>

#define BATCH 1024
#define T     336
#define PRED  96
#define D     64
#define HD    64
#define G     256
#define BT    8
#define NBLK  (BATCH / BT)
#define NTHR  256

// Scratch (device globals: allocation-free per harness rules)
__device__ float g_h1[(size_t)BATCH * T * HD];     // layer-0 hidden states (88 MB)
__device__ float g_h2last[BATCH * HD];             // layer-1 final hidden state

__device__ __forceinline__ float fast_sigmoid(float x) {
    return 1.0f / (1.0f + __expf(-x));
}
__device__ __forceinline__ float fast_tanh(float x) {
    // tanh(|x|) via exp, sign restored — avoids inf/inf NaN for large |x|
    float ax = fabsf(x);
    float e  = __expf(-2.0f * ax);
    float r  = (1.0f - e) / (1.0f + e);
    return copysignf(r, x);
}

// ---------------------------------------------------------------------------
// Encoder layer scan. One block = 8 batch rows. 256 threads = 1 thread/gate.
// Fuses the input GEMM (x @ W_ih^T) and recurrent GEMM (h @ W_hh^T) per step.
// ---------------------------------------------------------------------------
template <bool WRITE_ALL>
__global__ void __launch_bounds__(NTHR, 1) lstm_scan(
    const float* __restrict__ xin,    // [BATCH, T, D]
    const float* __restrict__ Wih,    // [G, D]
    const float* __restrict__ Whh,    // [G, HD]
    const float* __restrict__ bih,    // [G]
    const float* __restrict__ bhh,    // [G]
    float* __restrict__ hout)         // WRITE_ALL ? [BATCH,T,HD] : [BATCH,HD]
{
    extern __shared__ float sm[];
    float* sWih  = sm;                      // [64][256]  k-major
    float* sWhh  = sWih + 64 * G;           // [64][256]
    float* sX    = sWhh + 64 * G;           // [8][64]
    float* sH    = sX  + BT * 64;           // [8][64]
    float* sC    = sH  + BT * 64;           // [8][64]
    float* sGate = sC  + BT * 64;           // [8][256]
    float* sBias = sGate + BT * G;          // [256]

    const int tid = threadIdx.x;
    const int b0  = blockIdx.x * BT;

    // Load weights transposed to [k][g]: thread owns gate row g = tid
    {
        const float* wi = Wih + tid * D;
        const float* wh = Whh + tid * HD;
        #pragma unroll
        for (int k = 0; k < 64; k++) {
            sWih[k * G + tid] = wi[k];
            sWhh[k * G + tid] = wh[k];
        }
        sBias[tid] = bih[tid] + bhh[tid];
    }
    for (int i = tid; i < BT * HD; i += NTHR) { sH[i] = 0.0f; sC[i] = 0.0f; }
    // Preload x for t = 0
    if (tid < 128) {
        int b = tid >> 4, kq = (tid & 15) * 4;
        *(float4*)&sX[b * 64 + kq] =
            *(const float4*)&xin[(size_t)(b0 + b) * T * D + kq];
    }
    __syncthreads();

    const int g  = tid;
    const int gt = g >> 6;   // 0=i 1=f 2=g 3=o

    for (int t = 0; t < T; t++) {
        float acc[BT];
        {
            float bias = sBias[g];
            #pragma unroll
            for (int b = 0; b < BT; b++) acc[b] = bias;
        }
        #pragma unroll
        for (int k = 0; k < 64; k += 4) {
            float wi0 = sWih[(k + 0) * G + g], wi1 = sWih[(k + 1) * G + g];
            float wi2 = sWih[(k + 2) * G + g], wi3 = sWih[(k + 3) * G + g];
            float wh0 = sWhh[(k + 0) * G + g], wh1 = sWhh[(k + 1) * G + g];
            float wh2 = sWhh[(k + 2) * G + g], wh3 = sWhh[(k + 3) * G + g];
            #pragma unroll
            for (int b = 0; b < BT; b++) {
                float4 xv = *(const float4*)&sX[b * 64 + k];
                float4 hv = *(const float4*)&sH[b * 64 + k];
                acc[b] = fmaf(wi0, xv.x, acc[b]); acc[b] = fmaf(wh0, hv.x, acc[b]);
                acc[b] = fmaf(wi1, xv.y, acc[b]); acc[b] = fmaf(wh1, hv.y, acc[b]);
                acc[b] = fmaf(wi2, xv.z, acc[b]); acc[b] = fmaf(wh2, hv.z, acc[b]);
                acc[b] = fmaf(wi3, xv.w, acc[b]); acc[b] = fmaf(wh3, hv.w, acc[b]);
            }
        }
        // Activate gates
        #pragma unroll
        for (int b = 0; b < BT; b++) {
            float v = acc[b];
            sGate[b * G + g] = (gt == 2) ? fast_tanh(v) : fast_sigmoid(v);
        }
        __syncthreads();

        // h/c update + global write + prefetch next x
        #pragma unroll
        for (int p = tid; p < BT * HD; p += NTHR) {
            int b = p >> 6, j = p & 63;
            float iv = sGate[b * G + j];
            float fv = sGate[b * G + 64 + j];
            float gv = sGate[b * G + 128 + j];
            float ov = sGate[b * G + 192 + j];
            float c  = fmaf(fv, sC[p], iv * gv);
            sC[p] = c;
            float h = ov * fast_tanh(c);
            sH[p] = h;
            if (WRITE_ALL) {
                hout[(size_t)(b0 + b) * T * HD + (size_t)t * HD + j] = h;
            } else if (t == T - 1) {
                hout[(b0 + b) * HD + j] = h;
            }
        }
        if (t + 1 < T && tid < 128) {
            int b = tid >> 4, kq = (tid & 15) * 4;
            *(float4*)&sX[b * 64 + kq] =
                *(const float4*)&xin[(size_t)(b0 + b) * T * D + (size_t)(t + 1) * D + kq];
        }
        __syncthreads();
    }
}

// ---------------------------------------------------------------------------
// Decoder: one zero-state LSTM cell (c = i*g, h = o*tanh(c))
// ---------------------------------------------------------------------------
__device__ __forceinline__ void cell_zero_state(
    const float* __restrict__ sW,   // [64][256] k-major
    const float* __restrict__ sB,   // [256]
    const float* __restrict__ src,  // [8][64]
    float* __restrict__ dst,        // [8][64] (may alias src)
    float* __restrict__ sGate,      // [8][256]
    int tid)
{
    const int g = tid, gt = g >> 6;
    float acc[BT];
    {
        float bias = sB[g];
        #pragma unroll
        for (int b = 0; b < BT; b++) acc[b] = bias;
    }
    #pragma unroll
    for (int k = 0; k < 64; k += 4) {
        float w0 = sW[(k + 0) * G + g], w1 = sW[(k + 1) * G + g];
        float w2 = sW[(k + 2) * G + g], w3 = sW[(k + 3) * G + g];
        #pragma unroll
        for (int b = 0; b < BT; b++) {
            float4 v = *(const float4*)&src[b * 64 + k];
            acc[b] = fmaf(w0, v.x, acc[b]); acc[b] = fmaf(w1, v.y, acc[b]);
            acc[b] = fmaf(w2, v.z, acc[b]); acc[b] = fmaf(w3, v.w, acc[b]);
        }
    }
    #pragma unroll
    for (int b = 0; b < BT; b++) {
        float v = acc[b];
        sGate[b * G + g] = (gt == 2) ? fast_tanh(v) : fast_sigmoid(v);
    }
    __syncthreads();
    #pragma unroll
    for (int p = tid; p < BT * HD; p += NTHR) {
        int b = p >> 6, j = p & 63;
        float iv = sGate[b * G + j];
        float gv = sGate[b * G + 128 + j];
        float ov = sGate[b * G + 192 + j];
        float c  = iv * gv;
        dst[p]   = ov * fast_tanh(c);
    }
    __syncthreads();
}

__global__ void __launch_bounds__(NTHR, 1) lstm_decoder(
    const float* __restrict__ Wih0, const float* __restrict__ bih0, const float* __restrict__ bhh0,
    const float* __restrict__ Wih1, const float* __restrict__ bih1, const float* __restrict__ bhh1,
    const float* __restrict__ Wfc,  const float* __restrict__ bfc,
    const float* __restrict__ h2last,
    float* __restrict__ out)   // [BATCH, PRED, HD]
{
    extern __shared__ float sm[];
    float* sW0   = sm;                   // [64][256]
    float* sW1   = sW0  + 64 * G;        // [64][256]
    float* sWfc  = sW1  + 64 * G;        // [64][64] k-major
    float* sB0   = sWfc + 64 * 64;       // [256]
    float* sB1   = sB0  + G;             // [256]
    float* sBfc  = sB1  + G;             // [64]
    float* sIn   = sBfc + 64;            // [8][64]
    float* sHm   = sIn  + BT * 64;       // [8][64]
    float* sGate = sHm  + BT * 64;       // [8][256]

    const int tid = threadIdx.x;
    const int b0  = blockIdx.x * BT;

    {
        const float* w0 = Wih0 + tid * D;
        const float* w1 = Wih1 + tid * HD;
        #pragma unroll
        for (int k = 0; k < 64; k++) {
            sW0[k * G + tid] = w0[k];
            sW1[k * G + tid] = w1[k];
        }
        sB0[tid] = bih0[tid] + bhh0[tid];
        sB1[tid] = bih1[tid] + bhh1[tid];
        if (tid < 64) {
            sBfc[tid] = bfc[tid];
            for (int k = 0; k < 64; k++) sWfc[k * 64 + tid] = Wfc[tid * 64 + k];
        }
    }
    for (int i = tid; i < BT * HD; i += NTHR) sIn[i] = h2last[b0 * HD + i];
    __syncthreads();

    const int j  = tid & 63;
    const int bq = tid >> 6;
    const int ba = bq * 2, bb = ba + 1;

    for (int s = 0; s < PRED; s++) {
        cell_zero_state(sW0, sB0, sIn, sHm, sGate, tid);
        cell_zero_state(sW1, sB1, sHm, sHm, sGate, tid);

        // FC: pred = h @ W_fc^T + b_fc ; thread covers (j, {ba, bb})
        float a0 = sBfc[j], a1 = a0;
        #pragma unroll
        for (int k = 0; k < 64; k += 4) {
            float w0 = sWfc[(k + 0) * 64 + j], w1 = sWfc[(k + 1) * 64 + j];
            float w2 = sWfc[(k + 2) * 64 + j], w3 = sWfc[(k + 3) * 64 + j];
            float4 va = *(const float4*)&sHm[ba * 64 + k];
            float4 vb = *(const float4*)&sHm[bb * 64 + k];
            a0 = fmaf(w0, va.x, a0); a0 = fmaf(w1, va.y, a0);
            a0 = fmaf(w2, va.z, a0); a0 = fmaf(w3, va.w, a0);
            a1 = fmaf(w0, vb.x, a1); a1 = fmaf(w1, vb.y, a1);
            a1 = fmaf(w2, vb.z, a1); a1 = fmaf(w3, vb.w, a1);
        }
        out[(size_t)(b0 + ba) * PRED * HD + (size_t)s * HD + j] = a0;
        out[(size_t)(b0 + bb) * PRED * HD + (size_t)s * HD + j] = a1;
        sIn[ba * 64 + j] = a0;
        sIn[bb * 64 + j] = a1;
        __syncthreads();
    }
}

// ---------------------------------------------------------------------------
extern "C" void kernel_launch(void* const* d_in, const int* in_sizes, int n_in,
                              void* d_out, int out_size)
{
    const float* x    = (const float*)d_in[0];
    const float* Wih0 = (const float*)d_in[1];
    const float* Whh0 = (const float*)d_in[2];
    const float* bih0 = (const float*)d_in[3];
    const float* bhh0 = (const float*)d_in[4];
    const float* Wih1 = (const float*)d_in[5];
    const float* Whh1 = (const float*)d_in[6];
    const float* bih1 = (const float*)d_in[7];
    const float* bhh1 = (const float*)d_in[8];
    const float* Wfc  = (const float*)d_in[9];
    const float* bfc  = (const float*)d_in[10];
    float* out = (float*)d_out;

    float *h1 = nullptr, *h2l = nullptr;
    cudaGetSymbolAddress((void**)&h1,  g_h1);
    cudaGetSymbolAddress((void**)&h2l, g_h2last);

    const size_t smScan = (size_t)(2 * 64 * G + 3 * BT * 64 + BT * G + G) * sizeof(float);
    const size_t smDec  = (size_t)(2 * 64 * G + 64 * 64 + 2 * G + 64 + 2 * BT * 64 + BT * G) * sizeof(float);

    cudaFuncSetAttribute(lstm_scan<true>,  cudaFuncAttributeMaxDynamicSharedMemorySize, (int)smScan);
    cudaFuncSetAttribute(lstm_scan<false>, cudaFuncAttributeMaxDynamicSharedMemorySize, (int)smScan);
    cudaFuncSetAttribute(lstm_decoder,     cudaFuncAttributeMaxDynamicSharedMemorySize, (int)smDec);

    lstm_scan<true ><<<NBLK, NTHR, smScan>>>(x,  Wih0, Whh0, bih0, bhh0, h1);
    lstm_scan<false><<<NBLK, NTHR, smScan>>>(h1, Wih1, Whh1, bih1, bhh1, h2l);
    lstm_decoder<<<NBLK, NTHR, smDec>>>(Wih0, bih0, bhh0, Wih1, bih1, bhh1,
                                        Wfc, bfc, h2l, out);
}

// round 2
// speedup vs baseline: 1.3129x; 1.3129x over previous
#include <cuda_runtime.h>

#define BATCH 1024
#define T     336
#define PRED  96
#define D     64
#define HD    64
#define G     256
#define BT    8
#define NBLK  (BATCH / BT)
#define NTHR  256
#define NROWS (BATCH * T)          // 344064 rows per encoder layer
#define GROWS 16                   // rows per GEMM tile

typedef unsigned long long ull;

// Scratch (device globals: allocation-free per harness rules)
__device__ float g_p[(size_t)BATCH * T * G];       // precomputed gate pre-acts (352 MB)
__device__ float g_h1[(size_t)BATCH * T * HD];     // layer-0 hidden states (88 MB)
__device__ float g_h2last[BATCH * HD];             // layer-1 final hidden state

// Packed fp32x2 FMA (Blackwell FFMA2 — PTX-only, ptxas won't auto-fuse)
#define FMA2(acc, a, b) \
    asm("fma.rn.f32x2 %0, %1, %2, %0;" : "+l"(acc) : "l"(a), "l"(b))
#define UNPACK2(lo, hi, v) \
    asm("mov.b64 {%0, %1}, %2;" : "=f"(lo), "=f"(hi) : "l"(v))

__device__ __forceinline__ float fast_sigmoid(float x) {
    return 1.0f / (1.0f + __expf(-x));
}
__device__ __forceinline__ float fast_tanh(float x) {
    float ax = fabsf(x);
    float e  = __expf(-2.0f * ax);
    float r  = (1.0f - e) / (1.0f + e);
    return copysignf(r, x);
}

// ---------------------------------------------------------------------------
// Input GEMM (persistent): P[r][g] = sum_k In[r][k]*W[g][k] + b1[g] + b2[g]
// Weights live in registers (32 k-pairs per thread). f32x2 along k.
// ---------------------------------------------------------------------------
__global__ void __launch_bounds__(NTHR, 1) input_gemm(
    const float* __restrict__ In,   // [N, 64]
    const float* __restrict__ W,    // [256, 64]
    const float* __restrict__ b1,
    const float* __restrict__ b2,
    float* __restrict__ P,          // [N, 256]
    int N)
{
    __shared__ __align__(16) float sX[2][GROWS * 64];

    const int tid = threadIdx.x;

    ull w[32];
    {
        const ull* wp = (const ull*)(W + tid * 64);
        #pragma unroll
        for (int i = 0; i < 32; i++) w[i] = wp[i];
    }
    const float bias = b1[tid] + b2[tid];

    const int ntiles = N / GROWS;
    const int stride = gridDim.x;
    int tile = blockIdx.x;
    if (tile >= ntiles) return;

    // Preload first tile
    float4 xr = *(const float4*)(In + (size_t)tile * (GROWS * 64) + tid * 4);
    *(float4*)&sX[0][tid * 4] = xr;
    __syncthreads();

    int buf = 0;
    for (; tile < ntiles; tile += stride) {
        const int nxt = tile + stride;
        if (nxt < ntiles)
            xr = *(const float4*)(In + (size_t)nxt * (GROWS * 64) + tid * 4);

        ull acc[GROWS];
        #pragma unroll
        for (int r = 0; r < GROWS; r++) acc[r] = 0ull;

        const float* xb = sX[buf];
        #pragma unroll
        for (int kg = 0; kg < 16; kg++) {
            ull w01 = w[2 * kg], w23 = w[2 * kg + 1];
            #pragma unroll
            for (int r = 0; r < GROWS; r++) {
                ulonglong2 xv = *(const ulonglong2*)&xb[r * 64 + kg * 4];
                FMA2(acc[r], w01, xv.x);
                FMA2(acc[r], w23, xv.y);
            }
        }

        if (nxt < ntiles)
            *(float4*)&sX[buf ^ 1][tid * 4] = xr;

        float* prow = P + (size_t)tile * GROWS * G + tid;
        #pragma unroll
        for (int r = 0; r < GROWS; r++) {
            float lo, hi;
            UNPACK2(lo, hi, acc[r]);
            prow[(size_t)r * G] = lo + hi + bias;
        }
        __syncthreads();
        buf ^= 1;
    }
}

// ---------------------------------------------------------------------------
// Recurrent scan: gates = P[b][t][:] + h @ W_hh^T. W_hh rows in registers.
// One block = 8 batch rows, 256 threads = 1 thread per gate.
// ---------------------------------------------------------------------------
template <bool WRITE_ALL>
__global__ void __launch_bounds__(NTHR, 1) lstm_recur(
    const float* __restrict__ P,     // [BATCH, T, 256]  (includes biases)
    const float* __restrict__ Whh,   // [256, 64]
    float* __restrict__ hout)        // WRITE_ALL ? [BATCH,T,64] : [BATCH,64]
{
    __shared__ __align__(16) float sH[BT * 64];
    __shared__ __align__(16) float sC[BT * 64];
    __shared__ __align__(16) float sGate[BT * G];

    const int tid = threadIdx.x;
    const int b0  = blockIdx.x * BT;
    const int g   = tid;
    const int gt  = g >> 6;          // 0=i 1=f 2=g 3=o (warp-uniform)

    ull w[32];
    {
        const ull* wp = (const ull*)(Whh + g * 64);
        #pragma unroll
        for (int i = 0; i < 32; i++) w[i] = wp[i];
    }

    #pragma unroll
    for (int i = tid; i < BT * 64; i += NTHR) { sH[i] = 0.0f; sC[i] = 0.0f; }

    // per-batch P row pointers for this gate
    const float* pptr[BT];
    #pragma unroll
    for (int b = 0; b < BT; b++)
        pptr[b] = P + ((size_t)(b0 + b) * T) * G + g;

    float pc[BT];
    #pragma unroll
    for (int b = 0; b < BT; b++) pc[b] = pptr[b][0];
    __syncthreads();

    for (int t = 0; t < T; t++) {
        // prefetch next step's pre-activations
        float pn[BT];
        if (t + 1 < T) {
            #pragma unroll
            for (int b = 0; b < BT; b++) pn[b] = pptr[b][(size_t)(t + 1) * G];
        }

        ull acc[BT];
        #pragma unroll
        for (int b = 0; b < BT; b++) acc[b] = 0ull;

        #pragma unroll
        for (int kg = 0; kg < 16; kg++) {
            ull w01 = w[2 * kg], w23 = w[2 * kg + 1];
            #pragma unroll
            for (int b = 0; b < BT; b++) {
                ulonglong2 hv = *(const ulonglong2*)&sH[b * 64 + kg * 4];
                FMA2(acc[b], w01, hv.x);
                FMA2(acc[b], w23, hv.y);
            }
        }

        #pragma unroll
        for (int b = 0; b < BT; b++) {
            float lo, hi;
            UNPACK2(lo, hi, acc[b]);
            float v = lo + hi + pc[b];
            sGate[b * G + g] = (gt == 2) ? fast_tanh(v) : fast_sigmoid(v);
        }
        __syncthreads();

        #pragma unroll
        for (int p = tid; p < BT * 64; p += NTHR) {
            int b = p >> 6, j = p & 63;
            float iv = sGate[b * G + j];
            float fv = sGate[b * G + 64 + j];
            float gv = sGate[b * G + 128 + j];
            float ov = sGate[b * G + 192 + j];
            float c  = fmaf(fv, sC[p], iv * gv);
            sC[p] = c;
            float h = ov * fast_tanh(c);
            sH[p] = h;
            if (WRITE_ALL) {
                hout[(size_t)(b0 + b) * T * HD + (size_t)t * HD + j] = h;
            } else if (t == T - 1) {
                hout[(b0 + b) * HD + j] = h;
            }
        }
        __syncthreads();

        #pragma unroll
        for (int b = 0; b < BT; b++) pc[b] = pn[b];
    }
}

// ---------------------------------------------------------------------------
// Decoder: 96 steps of (zero-state cell0, zero-state cell1, FC). Both weight
// matrices in registers (128 regs/thread).
// ---------------------------------------------------------------------------
__device__ __forceinline__ void cell_zero_state_reg(
    const ull w[32], float bias, int gt, int tid,
    const float* __restrict__ src,   // [8][64] smem
    float* __restrict__ dst,         // [8][64] smem (may alias src)
    float* __restrict__ sGate)       // [8][256] smem
{
    ull acc[BT];
    #pragma unroll
    for (int b = 0; b < BT; b++) acc[b] = 0ull;

    #pragma unroll
    for (int kg = 0; kg < 16; kg++) {
        ull w01 = w[2 * kg], w23 = w[2 * kg + 1];
        #pragma unroll
        for (int b = 0; b < BT; b++) {
            ulonglong2 xv = *(const ulonglong2*)&src[b * 64 + kg * 4];
            FMA2(acc[b], w01, xv.x);
            FMA2(acc[b], w23, xv.y);
        }
    }
    #pragma unroll
    for (int b = 0; b < BT; b++) {
        float lo, hi;
        UNPACK2(lo, hi, acc[b]);
        float v = lo + hi + bias;
        sGate[b * G + threadIdx.x] = (gt == 2) ? fast_tanh(v) : fast_sigmoid(v);
    }
    __syncthreads();
    #pragma unroll
    for (int p = tid; p < BT * 64; p += NTHR) {
        int b = p >> 6, j = p & 63;
        float iv = sGate[b * G + j];
        float gv = sGate[b * G + 128 + j];
        float ov = sGate[b * G + 192 + j];
        dst[p] = ov * fast_tanh(iv * gv);
    }
    __syncthreads();
}

__global__ void __launch_bounds__(NTHR, 1) lstm_decoder(
    const float* __restrict__ Wih0, const float* __restrict__ bih0, const float* __restrict__ bhh0,
    const float* __restrict__ Wih1, const float* __restrict__ bih1, const float* __restrict__ bhh1,
    const float* __restrict__ Wfc,  const float* __restrict__ bfc,
    const float* __restrict__ h2last,
    float* __restrict__ out)   // [BATCH, PRED, 64]
{
    __shared__ __align__(16) float sWfc[64 * 64];   // k-major [k][j]
    __shared__ float sBfc[64];
    __shared__ __align__(16) float sIn[BT * 64];
    __shared__ __align__(16) float sHm[BT * 64];
    __shared__ __align__(16) float sGate[BT * G];

    const int tid = threadIdx.x;
    const int b0  = blockIdx.x * BT;
    const int gt  = tid >> 6;

    ull wa[32], wb[32];
    {
        const ull* w0 = (const ull*)(Wih0 + tid * 64);
        const ull* w1 = (const ull*)(Wih1 + tid * 64);
        #pragma unroll
        for (int i = 0; i < 32; i++) { wa[i] = w0[i]; wb[i] = w1[i]; }
    }
    const float bias0 = bih0[tid] + bhh0[tid];
    const float bias1 = bih1[tid] + bhh1[tid];

    if (tid < 64) {
        sBfc[tid] = bfc[tid];
        for (int k = 0; k < 64; k++) sWfc[k * 64 + tid] = Wfc[tid * 64 + k];
    }
    #pragma unroll
    for (int i = tid; i < BT * 64; i += NTHR) sIn[i] = h2last[b0 * 64 + i];
    __syncthreads();

    const int j  = tid & 63;
    const int bq = tid >> 6;
    const int ba = bq * 2, bb = ba + 1;

    for (int s = 0; s < PRED; s++) {
        cell_zero_state_reg(wa, bias0, gt, tid, sIn, sHm, sGate);
        cell_zero_state_reg(wb, bias1, gt, tid, sHm, sHm, sGate);

        // FC: pred = h @ W_fc^T + b_fc ; thread covers (j, {ba, bb})
        float a0 = sBfc[j], a1 = a0;
        #pragma unroll
        for (int k = 0; k < 64; k += 4) {
            float w0 = sWfc[(k + 0) * 64 + j], w1 = sWfc[(k + 1) * 64 + j];
            float w2 = sWfc[(k + 2) * 64 + j], w3 = sWfc[(k + 3) * 64 + j];
            float4 va = *(const float4*)&sHm[ba * 64 + k];
            float4 vb = *(const float4*)&sHm[bb * 64 + k];
            a0 = fmaf(w0, va.x, a0); a0 = fmaf(w1, va.y, a0);
            a0 = fmaf(w2, va.z, a0); a0 = fmaf(w3, va.w, a0);
            a1 = fmaf(w0, vb.x, a1); a1 = fmaf(w1, vb.y, a1);
            a1 = fmaf(w2, vb.z, a1); a1 = fmaf(w3, vb.w, a1);
        }
        out[(size_t)(b0 + ba) * PRED * HD + (size_t)s * HD + j] = a0;
        out[(size_t)(b0 + bb) * PRED * HD + (size_t)s * HD + j] = a1;
        sIn[ba * 64 + j] = a0;
        sIn[bb * 64 + j] = a1;
        __syncthreads();
    }
}

// ---------------------------------------------------------------------------
extern "C" void kernel_launch(void* const* d_in, const int* in_sizes, int n_in,
                              void* d_out, int out_size)
{
    const float* x    = (const float*)d_in[0];
    const float* Wih0 = (const float*)d_in[1];
    const float* Whh0 = (const float*)d_in[2];
    const float* bih0 = (const float*)d_in[3];
    const float* bhh0 = (const float*)d_in[4];
    const float* Wih1 = (const float*)d_in[5];
    const float* Whh1 = (const float*)d_in[6];
    const float* bih1 = (const float*)d_in[7];
    const float* bhh1 = (const float*)d_in[8];
    const float* Wfc  = (const float*)d_in[9];
    const float* bfc  = (const float*)d_in[10];
    float* out = (float*)d_out;

    float *pbuf = nullptr, *h1 = nullptr, *h2l = nullptr;
    cudaGetSymbolAddress((void**)&pbuf, g_p);
    cudaGetSymbolAddress((void**)&h1,   g_h1);
    cudaGetSymbolAddress((void**)&h2l,  g_h2last);

    // Layer 0: input GEMM over all (b,t), then recurrent scan
    input_gemm<<<148, NTHR>>>(x, Wih0, bih0, bhh0, pbuf, NROWS);
    lstm_recur<true ><<<NBLK, NTHR>>>(pbuf, Whh0, h1);

    // Layer 1: input GEMM on h1, then recurrent scan (keep only last h)
    input_gemm<<<148, NTHR>>>(h1, Wih1, bih1, bhh1, pbuf, NROWS);
    lstm_recur<false><<<NBLK, NTHR>>>(pbuf, Whh1, h2l);

    // Decoder
    lstm_decoder<<<NBLK, NTHR>>>(Wih0, bih0, bhh0, Wih1, bih1, bhh1,
                                 Wfc, bfc, h2l, out);
}

// round 3
// speedup vs baseline: 1.5158x; 1.1546x over previous
#include <cuda_runtime.h>

#define BATCH 1024
#define T     336
#define PRED  96
#define D     64
#define HD    64
#define G     256
#define BT    8
#define NBLK  (BATCH / BT)
#define NROWS (BATCH * T)
#define GROWS 16

typedef unsigned long long ull;

// Scratch (device globals: allocation-free per harness rules)
__device__ float g_p[(size_t)BATCH * T * G];       // gate pre-acts (352 MB)
__device__ float g_h1[(size_t)BATCH * T * HD];     // layer-0 hidden states (88 MB)
__device__ float g_h2last[BATCH * HD];

// Packed fp32x2 FMA (Blackwell — PTX-only)
#define FMA2(acc, a, b) \
    asm("fma.rn.f32x2 %0, %1, %2, %0;" : "+l"(acc) : "l"(a), "l"(b))
#define UNPACK2(lo, hi, v) \
    asm("mov.b64 {%0, %1}, %2;" : "=f"(lo), "=f"(hi) : "l"(v))

__device__ __forceinline__ float fast_sigmoid(float x) {
    return 1.0f / (1.0f + __expf(-x));
}
__device__ __forceinline__ float fast_tanh(float x) {
    float ax = fabsf(x);
    float e  = __expf(-2.0f * ax);
    float r  = (1.0f - e) / (1.0f + e);
    return copysignf(r, x);
}

// ---------------------------------------------------------------------------
// Input GEMM (persistent, 512 thr): P[r][g] = In[r][:]·W[g][:] + b1[g] + b2[g]
// thread = (gate g, row-half rh). Weights in 64 regs. 16-row tiles.
// ---------------------------------------------------------------------------
__global__ void __launch_bounds__(512, 1) input_gemm(
    const float* __restrict__ In,   // [N, 64]
    const float* __restrict__ W,    // [256, 64]
    const float* __restrict__ b1,
    const float* __restrict__ b2,
    float* __restrict__ P,          // [N, 256]
    int N)
{
    __shared__ __align__(16) float sX[2][GROWS * 64];

    const int tid = threadIdx.x;
    const int g   = tid & 255;
    const int rh  = tid >> 8;       // 0/1: rows [0,8) or [8,16) of tile

    ull w[32];
    {
        const ull* wp = (const ull*)(W + g * 64);
        #pragma unroll
        for (int i = 0; i < 32; i++) w[i] = wp[i];
    }
    const float bias = b1[g] + b2[g];

    const int ntiles = N / GROWS;
    const int stride = gridDim.x;
    int tile = blockIdx.x;
    if (tile >= ntiles) return;

    float2 xr = *(const float2*)(In + (size_t)tile * (GROWS * 64) + tid * 2);
    *(float2*)&sX[0][tid * 2] = xr;
    __syncthreads();

    int buf = 0;
    for (; tile < ntiles; tile += stride) {
        const int nxt = tile + stride;
        if (nxt < ntiles)
            xr = *(const float2*)(In + (size_t)nxt * (GROWS * 64) + tid * 2);

        ull acc[8];
        #pragma unroll
        for (int r = 0; r < 8; r++) acc[r] = 0ull;

        const float* xb = sX[buf] + rh * (8 * 64);
        #pragma unroll
        for (int kg = 0; kg < 16; kg++) {
            ull w01 = w[2 * kg], w23 = w[2 * kg + 1];
            #pragma unroll
            for (int r = 0; r < 8; r++) {
                ulonglong2 xv = *(const ulonglong2*)&xb[r * 64 + kg * 4];
                FMA2(acc[r], w01, xv.x);
                FMA2(acc[r], w23, xv.y);
            }
        }

        if (nxt < ntiles)
            *(float2*)&sX[buf ^ 1][tid * 2] = xr;

        float* prow = P + ((size_t)tile * GROWS + rh * 8) * G + g;
        #pragma unroll
        for (int r = 0; r < 8; r++) {
            float lo, hi;
            UNPACK2(lo, hi, acc[r]);
            __stcs(&prow[(size_t)r * G], lo + hi + bias);
        }
        __syncthreads();
        buf ^= 1;
    }
}

// ---------------------------------------------------------------------------
// Recurrent scan, 512 threads: thread = (gate g, batch-half bh) for the GEMM,
// and (eb, ej) for the cell update (c lives in a register).
// ---------------------------------------------------------------------------
template <bool WRITE_ALL>
__global__ void __launch_bounds__(512, 1) lstm_recur(
    const float* __restrict__ P,     // [BATCH, T, 256] (biases included)
    const float* __restrict__ Whh,   // [256, 64]
    float* __restrict__ hout)        // WRITE_ALL ? [BATCH,T,64] : [BATCH,64]
{
    __shared__ __align__(16) float sH[BT * 64];
    __shared__ __align__(16) float sGate[BT * G];

    const int tid = threadIdx.x;
    const int b0  = blockIdx.x * BT;
    const int g   = tid & 255;
    const int bh  = tid >> 8;            // batch rows [bh*4, bh*4+4)
    const int gt  = g >> 6;              // warp-uniform

    ull w[32];
    {
        const ull* wp = (const ull*)(Whh + g * 64);
        #pragma unroll
        for (int i = 0; i < 32; i++) w[i] = wp[i];
    }

    // cell-update identity: one (b,j) per thread, c in register
    const int eb = tid >> 6;
    const int ej = tid & 63;
    float c = 0.0f;

    sH[tid] = 0.0f;

    const float* pbase = P + ((size_t)(b0 + bh * 4) * T) * G + g;
    float pc[4];
    #pragma unroll
    for (int b = 0; b < 4; b++) pc[b] = pbase[(size_t)b * T * G];
    __syncthreads();

    for (int t = 0; t < T; t++) {
        float pn[4];
        if (t + 1 < T) {
            #pragma unroll
            for (int b = 0; b < 4; b++)
                pn[b] = __ldcs(&pbase[(size_t)b * T * G + (size_t)(t + 1) * G]);
        }

        ull acc[4];
        #pragma unroll
        for (int b = 0; b < 4; b++) acc[b] = 0ull;

        #pragma unroll
        for (int kg = 0; kg < 16; kg++) {
            ull w01 = w[2 * kg], w23 = w[2 * kg + 1];
            #pragma unroll
            for (int b = 0; b < 4; b++) {
                ulonglong2 hv = *(const ulonglong2*)&sH[(bh * 4 + b) * 64 + kg * 4];
                FMA2(acc[b], w01, hv.x);
                FMA2(acc[b], w23, hv.y);
            }
        }

        #pragma unroll
        for (int b = 0; b < 4; b++) {
            float lo, hi;
            UNPACK2(lo, hi, acc[b]);
            float v = lo + hi + pc[b];
            sGate[(bh * 4 + b) * G + g] = (gt == 2) ? fast_tanh(v) : fast_sigmoid(v);
        }
        __syncthreads();

        // cell update: thread (eb, ej)
        {
            float iv = sGate[eb * G + ej];
            float fv = sGate[eb * G + 64 + ej];
            float gv = sGate[eb * G + 128 + ej];
            float ov = sGate[eb * G + 192 + ej];
            c = fmaf(fv, c, iv * gv);
            float h = ov * fast_tanh(c);
            sH[tid] = h;
            if (WRITE_ALL) {
                hout[(size_t)(b0 + eb) * T * HD + (size_t)t * HD + ej] = h;
            } else if (t == T - 1) {
                hout[(b0 + eb) * HD + ej] = h;
            }
        }
        __syncthreads();

        #pragma unroll
        for (int b = 0; b < 4; b++) pc[b] = pn[b];
    }
}

// ---------------------------------------------------------------------------
// Decoder, 512 threads: cell0 weights in regs; cell1 + FC weights in smem as
// transposed ull pairs [kpair][col] (conflict-free, f32x2-ready).
// ---------------------------------------------------------------------------
__global__ void __launch_bounds__(512, 1) lstm_decoder(
    const float* __restrict__ Wih0, const float* __restrict__ bih0, const float* __restrict__ bhh0,
    const float* __restrict__ Wih1, const float* __restrict__ bih1, const float* __restrict__ bhh1,
    const float* __restrict__ Wfc,  const float* __restrict__ bfc,
    const float* __restrict__ h2last,
    float* __restrict__ out)   // [BATCH, PRED, 64]
{
    extern __shared__ __align__(16) char dyn[];
    ull*   sW1p  = (ull*)dyn;                      // [32][256] ull (64 KB)
    ull*   sWfcp = sW1p + 32 * 256;                // [32][64]  ull (16 KB)
    float* sB1   = (float*)(sWfcp + 32 * 64);      // [256]
    float* sBfc  = sB1 + 256;                      // [64]
    float* sIn   = sBfc + 64;                      // [8][64]
    float* sHm   = sIn + BT * 64;                  // [8][64]
    float* sGate = sHm + BT * 64;                  // [8][256]

    const int tid = threadIdx.x;
    const int b0  = blockIdx.x * BT;
    const int g   = tid & 255;
    const int bh  = tid >> 8;
    const int gt  = g >> 6;
    const int eb  = tid >> 6;
    const int ej  = tid & 63;

    ull wa[32];
    {
        const ull* w0 = (const ull*)(Wih0 + g * 64);
        #pragma unroll
        for (int i = 0; i < 32; i++) wa[i] = w0[i];
    }
    const float bias0 = bih0[g] + bhh0[g];

    // fill smem weight tables (transposed pair layout)
    if (tid < 256) {
        const ull* w1 = (const ull*)(Wih1 + tid * 64);
        #pragma unroll
        for (int i = 0; i < 32; i++) sW1p[i * 256 + tid] = w1[i];
        sB1[tid] = bih1[tid] + bhh1[tid];
    } else if (tid < 320) {
        int j = tid - 256;
        const ull* wf = (const ull*)(Wfc + j * 64);
        #pragma unroll
        for (int i = 0; i < 32; i++) sWfcp[i * 64 + j] = wf[i];
        sBfc[j] = bfc[j];
    }
    sIn[tid] = h2last[b0 * 64 + tid];
    __syncthreads();

    for (int s = 0; s < PRED; s++) {
        // ---- cell0 (weights in regs), src = sIn ----
        {
            ull acc[4];
            #pragma unroll
            for (int b = 0; b < 4; b++) acc[b] = 0ull;
            #pragma unroll
            for (int kg = 0; kg < 16; kg++) {
                ull w01 = wa[2 * kg], w23 = wa[2 * kg + 1];
                #pragma unroll
                for (int b = 0; b < 4; b++) {
                    ulonglong2 xv = *(const ulonglong2*)&sIn[(bh * 4 + b) * 64 + kg * 4];
                    FMA2(acc[b], w01, xv.x);
                    FMA2(acc[b], w23, xv.y);
                }
            }
            #pragma unroll
            for (int b = 0; b < 4; b++) {
                float lo, hi;
                UNPACK2(lo, hi, acc[b]);
                float v = lo + hi + bias0;
                sGate[(bh * 4 + b) * G + g] = (gt == 2) ? fast_tanh(v) : fast_sigmoid(v);
            }
            __syncthreads();
            float iv = sGate[eb * G + ej];
            float gv = sGate[eb * G + 128 + ej];
            float ov = sGate[eb * G + 192 + ej];
            sHm[tid] = ov * fast_tanh(iv * gv);
            __syncthreads();
        }
        // ---- cell1 (weights from smem), src = sHm ----
        {
            ull acc[4];
            #pragma unroll
            for (int b = 0; b < 4; b++) acc[b] = 0ull;
            #pragma unroll
            for (int kg = 0; kg < 16; kg++) {
                ull w01 = sW1p[(2 * kg) * 256 + g];
                ull w23 = sW1p[(2 * kg + 1) * 256 + g];
                #pragma unroll
                for (int b = 0; b < 4; b++) {
                    ulonglong2 xv = *(const ulonglong2*)&sHm[(bh * 4 + b) * 64 + kg * 4];
                    FMA2(acc[b], w01, xv.x);
                    FMA2(acc[b], w23, xv.y);
                }
            }
            float bias1 = sB1[g];
            #pragma unroll
            for (int b = 0; b < 4; b++) {
                float lo, hi;
                UNPACK2(lo, hi, acc[b]);
                float v = lo + hi + bias1;
                sGate[(bh * 4 + b) * G + g] = (gt == 2) ? fast_tanh(v) : fast_sigmoid(v);
            }
            __syncthreads();
            float iv = sGate[eb * G + ej];
            float gv = sGate[eb * G + 128 + ej];
            float ov = sGate[eb * G + 192 + ej];
            sHm[tid] = ov * fast_tanh(iv * gv);
            __syncthreads();
        }
        // ---- FC: one output per thread (eb, ej) ----
        {
            ull acc = 0ull;
            #pragma unroll
            for (int i = 0; i < 16; i++) {
                ull w01 = sWfcp[(2 * i) * 64 + ej];
                ull w23 = sWfcp[(2 * i + 1) * 64 + ej];
                ulonglong2 xv = *(const ulonglong2*)&sHm[eb * 64 + i * 4];
                FMA2(acc, w01, xv.x);
                FMA2(acc, w23, xv.y);
            }
            float lo, hi;
            UNPACK2(lo, hi, acc);
            float pred = lo + hi + sBfc[ej];
            out[(size_t)(b0 + eb) * PRED * HD + (size_t)s * HD + ej] = pred;
            sIn[tid] = pred;
            __syncthreads();
        }
    }
}

// ---------------------------------------------------------------------------
extern "C" void kernel_launch(void* const* d_in, const int* in_sizes, int n_in,
                              void* d_out, int out_size)
{
    const float* x    = (const float*)d_in[0];
    const float* Wih0 = (const float*)d_in[1];
    const float* Whh0 = (const float*)d_in[2];
    const float* bih0 = (const float*)d_in[3];
    const float* bhh0 = (const float*)d_in[4];
    const float* Wih1 = (const float*)d_in[5];
    const float* Whh1 = (const float*)d_in[6];
    const float* bih1 = (const float*)d_in[7];
    const float* bhh1 = (const float*)d_in[8];
    const float* Wfc  = (const float*)d_in[9];
    const float* bfc  = (const float*)d_in[10];
    float* out = (float*)d_out;

    float *pbuf = nullptr, *h1 = nullptr, *h2l = nullptr;
    cudaGetSymbolAddress((void**)&pbuf, g_p);
    cudaGetSymbolAddress((void**)&h1,   g_h1);
    cudaGetSymbolAddress((void**)&h2l,  g_h2last);

    const size_t smDec = (32 * 256 + 32 * 64) * sizeof(ull)
                       + (256 + 64 + BT * 64 * 2 + BT * G) * sizeof(float);
    cudaFuncSetAttribute(lstm_decoder, cudaFuncAttributeMaxDynamicSharedMemorySize, (int)smDec);

    input_gemm<<<148, 512>>>(x, Wih0, bih0, bhh0, pbuf, NROWS);
    lstm_recur<true ><<<NBLK, 512>>>(pbuf, Whh0, h1);

    input_gemm<<<148, 512>>>(h1, Wih1, bih1, bhh1, pbuf, NROWS);
    lstm_recur<false><<<NBLK, 512>>>(pbuf, Whh1, h2l);

    lstm_decoder<<<NBLK, 512, smDec>>>(Wih0, bih0, bhh0, Wih1, bih1, bhh1,
                                       Wfc, bfc, h2l, out);
}

// round 4
// speedup vs baseline: 1.5373x; 1.0142x over previous
#include <cuda_runtime.h>

#define BATCH 1024
#define T     336
#define PRED  96
#define D     64
#define HD    64
#define G     256
#define NROWS (BATCH * T)

typedef unsigned long long ull;

// Scratch (device globals: allocation-free per harness rules)
__device__ float g_p[(size_t)BATCH * T * G];       // gate pre-acts (352 MB)
__device__ float g_h1[(size_t)BATCH * T * HD];     // layer-0 hidden states (88 MB)
__device__ float g_h2last[BATCH * HD];

// Packed fp32x2 FMA (Blackwell — PTX-only)
#define FMA2(acc, a, b) \
    asm("fma.rn.f32x2 %0, %1, %2, %0;" : "+l"(acc) : "l"(a), "l"(b))
#define UNPACK2(lo, hi, v) \
    asm("mov.b64 {%0, %1}, %2;" : "=f"(lo), "=f"(hi) : "l"(v))

__device__ __forceinline__ float fast_sigmoid(float x) {
    return 1.0f / (1.0f + __expf(-x));
}
__device__ __forceinline__ float fast_tanh(float x) {
    float ax = fabsf(x);
    float e  = __expf(-2.0f * ax);
    float r  = (1.0f - e) / (1.0f + e);
    return copysignf(r, x);
}

// ---------------------------------------------------------------------------
// Input GEMM (persistent, 256 thr, 2 CTAs/SM): P[r][g] = In[r]·W[g] + b1 + b2
// Thread = gate g; 8-row tiles; weights in 64 regs; double-buffered sX.
// ---------------------------------------------------------------------------
__global__ void __launch_bounds__(256, 2) input_gemm(
    const float* __restrict__ In,   // [N, 64]
    const float* __restrict__ W,    // [256, 64]
    const float* __restrict__ b1,
    const float* __restrict__ b2,
    float* __restrict__ P,          // [N, 256]
    int N)
{
    __shared__ __align__(16) float sX[2][8 * 64];

    const int tid = threadIdx.x;
    const int g   = tid;

    ull w[32];
    {
        const ull* wp = (const ull*)(W + g * 64);
        #pragma unroll
        for (int i = 0; i < 32; i++) w[i] = wp[i];
    }
    const float bias = b1[g] + b2[g];

    const int ntiles = N / 8;
    const int stride = gridDim.x;
    int tile = blockIdx.x;
    if (tile >= ntiles) return;

    float2 xr = *(const float2*)(In + (size_t)tile * (8 * 64) + tid * 2);
    *(float2*)&sX[0][tid * 2] = xr;
    __syncthreads();

    int buf = 0;
    for (; tile < ntiles; tile += stride) {
        const int nxt = tile + stride;
        if (nxt < ntiles)
            xr = *(const float2*)(In + (size_t)nxt * (8 * 64) + tid * 2);

        ull acc[8];
        #pragma unroll
        for (int r = 0; r < 8; r++) acc[r] = 0ull;

        const float* xb = sX[buf];
        #pragma unroll
        for (int kg = 0; kg < 16; kg++) {
            ull w01 = w[2 * kg], w23 = w[2 * kg + 1];
            #pragma unroll
            for (int r = 0; r < 8; r++) {
                ulonglong2 xv = *(const ulonglong2*)&xb[r * 64 + kg * 4];
                FMA2(acc[r], w01, xv.x);
                FMA2(acc[r], w23, xv.y);
            }
        }

        if (nxt < ntiles)
            *(float2*)&sX[buf ^ 1][tid * 2] = xr;

        float* prow = P + (size_t)tile * 8 * G + g;
        #pragma unroll
        for (int r = 0; r < 8; r++) {
            float lo, hi;
            UNPACK2(lo, hi, acc[r]);
            __stcs(&prow[(size_t)r * G], lo + hi + bias);
        }
        __syncthreads();
        buf ^= 1;
    }
}

// ---------------------------------------------------------------------------
// Recurrent scan: BT=4 rows/CTA, 256 threads, grid=256 → 2 CTAs/SM.
// Thread = gate g for the GEMM (4 accs), (eb,ej) for the cell update.
// ---------------------------------------------------------------------------
template <bool WRITE_ALL>
__global__ void __launch_bounds__(256, 2) lstm_recur(
    const float* __restrict__ P,     // [BATCH, T, 256] (biases included)
    const float* __restrict__ Whh,   // [256, 64]
    float* __restrict__ hout)        // WRITE_ALL ? [BATCH,T,64] : [BATCH,64]
{
    __shared__ __align__(16) float sH[4 * 64];
    __shared__ __align__(16) float sGate[4 * G];

    const int tid = threadIdx.x;
    const int b0  = blockIdx.x * 4;
    const int g   = tid;
    const int gt  = g >> 6;              // warp-uniform

    ull w[32];
    {
        const ull* wp = (const ull*)(Whh + g * 64);
        #pragma unroll
        for (int i = 0; i < 32; i++) w[i] = wp[i];
    }

    const int eb = tid >> 6;             // 0..3
    const int ej = tid & 63;
    float c = 0.0f;

    sH[tid] = 0.0f;

    const float* pbase = P + ((size_t)b0 * T) * G + g;
    float pc[4];
    #pragma unroll
    for (int b = 0; b < 4; b++) pc[b] = pbase[(size_t)b * T * G];
    __syncthreads();

    for (int t = 0; t < T; t++) {
        float pn[4];
        if (t + 1 < T) {
            #pragma unroll
            for (int b = 0; b < 4; b++)
                pn[b] = __ldcs(&pbase[(size_t)b * T * G + (size_t)(t + 1) * G]);
        }

        ull acc[4];
        #pragma unroll
        for (int b = 0; b < 4; b++) acc[b] = 0ull;

        #pragma unroll
        for (int kg = 0; kg < 16; kg++) {
            ull w01 = w[2 * kg], w23 = w[2 * kg + 1];
            #pragma unroll
            for (int b = 0; b < 4; b++) {
                ulonglong2 hv = *(const ulonglong2*)&sH[b * 64 + kg * 4];
                FMA2(acc[b], w01, hv.x);
                FMA2(acc[b], w23, hv.y);
            }
        }

        #pragma unroll
        for (int b = 0; b < 4; b++) {
            float lo, hi;
            UNPACK2(lo, hi, acc[b]);
            float v = lo + hi + pc[b];
            sGate[b * G + g] = (gt == 2) ? fast_tanh(v) : fast_sigmoid(v);
        }
        __syncthreads();

        {
            float iv = sGate[eb * G + ej];
            float fv = sGate[eb * G + 64 + ej];
            float gv = sGate[eb * G + 128 + ej];
            float ov = sGate[eb * G + 192 + ej];
            c = fmaf(fv, c, iv * gv);
            float h = ov * fast_tanh(c);
            sH[tid] = h;
            if (WRITE_ALL) {
                hout[(size_t)(b0 + eb) * T * HD + (size_t)t * HD + ej] = h;
            } else if (t == T - 1) {
                hout[(b0 + eb) * HD + ej] = h;
            }
        }
        __syncthreads();

        #pragma unroll
        for (int b = 0; b < 4; b++) pc[b] = pn[b];
    }
}

// ---------------------------------------------------------------------------
// Decoder: 512 threads, BT=8. Half-split register weights:
// warps 0-7 hold W_ih0 rows, warps 8-15 hold W_ih1 rows. FC from packed smem.
// ---------------------------------------------------------------------------
__global__ void __launch_bounds__(512, 1) lstm_decoder(
    const float* __restrict__ Wih0, const float* __restrict__ bih0, const float* __restrict__ bhh0,
    const float* __restrict__ Wih1, const float* __restrict__ bih1, const float* __restrict__ bhh1,
    const float* __restrict__ Wfc,  const float* __restrict__ bfc,
    const float* __restrict__ h2last,
    float* __restrict__ out)   // [BATCH, PRED, 64]
{
    __shared__ __align__(16) ull   sWfcp[32 * 64];   // [kpair][j] packed (16 KB)
    __shared__ float sBfc[64];
    __shared__ __align__(16) float sIn[8 * 64];
    __shared__ __align__(16) float sHm[8 * 64];
    __shared__ __align__(16) float sGate[8 * G];

    const int tid  = threadIdx.x;
    const int b0   = blockIdx.x * 8;
    const int half = tid >> 8;           // 0: cell0 gates, 1: cell1 gates
    const int hg   = tid & 255;          // gate index within half
    const int gt   = hg >> 6;
    const int eb   = tid >> 6;           // 0..7
    const int ej   = tid & 63;

    ull w[32];
    {
        const float* wsrc = half ? (Wih1 + hg * 64) : (Wih0 + hg * 64);
        const ull* wp = (const ull*)wsrc;
        #pragma unroll
        for (int i = 0; i < 32; i++) w[i] = wp[i];
    }
    const float bias = half ? (bih1[hg] + bhh1[hg]) : (bih0[hg] + bhh0[hg]);

    if (tid < 64) {
        const ull* wf = (const ull*)(Wfc + tid * 64);
        #pragma unroll
        for (int i = 0; i < 32; i++) sWfcp[i * 64 + tid] = wf[i];
        sBfc[tid] = bfc[tid];
    }
    sIn[tid] = h2last[b0 * 64 + tid];
    __syncthreads();

    for (int s = 0; s < PRED; s++) {
        // ---- cell0: lower half computes gates from sIn ----
        if (half == 0) {
            ull acc[8];
            #pragma unroll
            for (int b = 0; b < 8; b++) acc[b] = 0ull;
            #pragma unroll
            for (int kg = 0; kg < 16; kg++) {
                ull w01 = w[2 * kg], w23 = w[2 * kg + 1];
                #pragma unroll
                for (int b = 0; b < 8; b++) {
                    ulonglong2 xv = *(const ulonglong2*)&sIn[b * 64 + kg * 4];
                    FMA2(acc[b], w01, xv.x);
                    FMA2(acc[b], w23, xv.y);
                }
            }
            #pragma unroll
            for (int b = 0; b < 8; b++) {
                float lo, hi;
                UNPACK2(lo, hi, acc[b]);
                float v = lo + hi + bias;
                sGate[b * G + hg] = (gt == 2) ? fast_tanh(v) : fast_sigmoid(v);
            }
        }
        __syncthreads();
        {
            float iv = sGate[eb * G + ej];
            float gv = sGate[eb * G + 128 + ej];
            float ov = sGate[eb * G + 192 + ej];
            sHm[tid] = ov * fast_tanh(iv * gv);
        }
        __syncthreads();

        // ---- cell1: upper half computes gates from sHm ----
        if (half == 1) {
            ull acc[8];
            #pragma unroll
            for (int b = 0; b < 8; b++) acc[b] = 0ull;
            #pragma unroll
            for (int kg = 0; kg < 16; kg++) {
                ull w01 = w[2 * kg], w23 = w[2 * kg + 1];
                #pragma unroll
                for (int b = 0; b < 8; b++) {
                    ulonglong2 xv = *(const ulonglong2*)&sHm[b * 64 + kg * 4];
                    FMA2(acc[b], w01, xv.x);
                    FMA2(acc[b], w23, xv.y);
                }
            }
            #pragma unroll
            for (int b = 0; b < 8; b++) {
                float lo, hi;
                UNPACK2(lo, hi, acc[b]);
                float v = lo + hi + bias;
                sGate[b * G + hg] = (gt == 2) ? fast_tanh(v) : fast_sigmoid(v);
            }
        }
        __syncthreads();
        {
            float iv = sGate[eb * G + ej];
            float gv = sGate[eb * G + 128 + ej];
            float ov = sGate[eb * G + 192 + ej];
            sHm[tid] = ov * fast_tanh(iv * gv);
        }
        __syncthreads();

        // ---- FC: one output per thread (eb, ej) ----
        {
            ull acc = 0ull;
            #pragma unroll
            for (int i = 0; i < 16; i++) {
                ull w01 = sWfcp[(2 * i) * 64 + ej];
                ull w23 = sWfcp[(2 * i + 1) * 64 + ej];
                ulonglong2 xv = *(const ulonglong2*)&sHm[eb * 64 + i * 4];
                FMA2(acc, w01, xv.x);
                FMA2(acc, w23, xv.y);
            }
            float lo, hi;
            UNPACK2(lo, hi, acc);
            float pred = lo + hi + sBfc[ej];
            out[(size_t)(b0 + eb) * PRED * HD + (size_t)s * HD + ej] = pred;
            sIn[tid] = pred;
            __syncthreads();
        }
    }
}

// ---------------------------------------------------------------------------
extern "C" void kernel_launch(void* const* d_in, const int* in_sizes, int n_in,
                              void* d_out, int out_size)
{
    const float* x    = (const float*)d_in[0];
    const float* Wih0 = (const float*)d_in[1];
    const float* Whh0 = (const float*)d_in[2];
    const float* bih0 = (const float*)d_in[3];
    const float* bhh0 = (const float*)d_in[4];
    const float* Wih1 = (const float*)d_in[5];
    const float* Whh1 = (const float*)d_in[6];
    const float* bih1 = (const float*)d_in[7];
    const float* bhh1 = (const float*)d_in[8];
    const float* Wfc  = (const float*)d_in[9];
    const float* bfc  = (const float*)d_in[10];
    float* out = (float*)d_out;

    float *pbuf = nullptr, *h1 = nullptr, *h2l = nullptr;
    cudaGetSymbolAddress((void**)&pbuf, g_p);
    cudaGetSymbolAddress((void**)&h1,   g_h1);
    cudaGetSymbolAddress((void**)&h2l,  g_h2last);

    input_gemm<<<296, 256>>>(x, Wih0, bih0, bhh0, pbuf, NROWS);
    lstm_recur<true ><<<256, 256>>>(pbuf, Whh0, h1);

    input_gemm<<<296, 256>>>(h1, Wih1, bih1, bhh1, pbuf, NROWS);
    lstm_recur<false><<<256, 256>>>(pbuf, Whh1, h2l);

    lstm_decoder<<<128, 512>>>(Wih0, bih0, bhh0, Wih1, bih1, bhh1,
                               Wfc, bfc, h2l, out);
}

// round 5
// speedup vs baseline: 1.7560x; 1.1423x over previous
#include <cuda_runtime.h>

#define BATCH 1024
#define T     336
#define PRED  96
#define D     64
#define HD    64
#define G     256
#define NROWS (BATCH * T)

typedef unsigned long long ull;

// Scratch (device globals: allocation-free per harness rules)
__device__ float g_p[(size_t)BATCH * T * G];       // gate pre-acts (352 MB)
__device__ float g_h1[(size_t)BATCH * T * HD];     // layer-0 hidden states (88 MB)
__device__ float g_h2last[BATCH * HD];

// Packed fp32x2 FMA (Blackwell — PTX-only)
#define FMA2(acc, a, b) \
    asm("fma.rn.f32x2 %0, %1, %2, %0;" : "+l"(acc) : "l"(a), "l"(b))
#define UNPACK2(lo, hi, v) \
    asm("mov.b64 {%0, %1}, %2;" : "=f"(lo), "=f"(hi) : "l"(v))

// HW tanh unit: 1 MUFU, no RCP chain
__device__ __forceinline__ float fast_tanh(float x) {
    float y;
    asm("tanh.approx.f32 %0, %1;" : "=f"(y) : "f"(x));
    return y;
}
__device__ __forceinline__ float fast_sigmoid(float x) {
    return fmaf(fast_tanh(0.5f * x), 0.5f, 0.5f);
}

// ---------------------------------------------------------------------------
// Input GEMM (persistent, 256 thr, 2 CTAs/SM): P[r][g] = In[r]·W[g] + b1 + b2
// ---------------------------------------------------------------------------
__global__ void __launch_bounds__(256, 2) input_gemm(
    const float* __restrict__ In,   // [N, 64]
    const float* __restrict__ W,    // [256, 64]
    const float* __restrict__ b1,
    const float* __restrict__ b2,
    float* __restrict__ P,          // [N, 256]
    int N)
{
    __shared__ __align__(16) float sX[2][8 * 64];

    const int tid = threadIdx.x;
    const int g   = tid;

    ull w[32];
    {
        const ull* wp = (const ull*)(W + g * 64);
        #pragma unroll
        for (int i = 0; i < 32; i++) w[i] = wp[i];
    }
    const float bias = b1[g] + b2[g];

    const int ntiles = N / 8;
    const int stride = gridDim.x;
    int tile = blockIdx.x;
    if (tile >= ntiles) return;

    float2 xr = *(const float2*)(In + (size_t)tile * (8 * 64) + tid * 2);
    *(float2*)&sX[0][tid * 2] = xr;
    __syncthreads();

    int buf = 0;
    for (; tile < ntiles; tile += stride) {
        const int nxt = tile + stride;
        if (nxt < ntiles)
            xr = *(const float2*)(In + (size_t)nxt * (8 * 64) + tid * 2);

        ull acc[8];
        #pragma unroll
        for (int r = 0; r < 8; r++) acc[r] = 0ull;

        const float* xb = sX[buf];
        #pragma unroll
        for (int kg = 0; kg < 16; kg++) {
            ull w01 = w[2 * kg], w23 = w[2 * kg + 1];
            #pragma unroll
            for (int r = 0; r < 8; r++) {
                ulonglong2 xv = *(const ulonglong2*)&xb[r * 64 + kg * 4];
                FMA2(acc[r], w01, xv.x);
                FMA2(acc[r], w23, xv.y);
            }
        }

        if (nxt < ntiles)
            *(float2*)&sX[buf ^ 1][tid * 2] = xr;

        float* prow = P + (size_t)tile * 8 * G + g;
        #pragma unroll
        for (int r = 0; r < 8; r++) {
            float lo, hi;
            UNPACK2(lo, hi, acc[r]);
            __stcs(&prow[(size_t)r * G], lo + hi + bias);
        }
        __syncthreads();
        buf ^= 1;
    }
}

// ---------------------------------------------------------------------------
// Recurrent scan: BT=4 rows/CTA, 256 threads, grid=256 → 2 CTAs/SM.
// ---------------------------------------------------------------------------
template <bool WRITE_ALL>
__global__ void __launch_bounds__(256, 2) lstm_recur(
    const float* __restrict__ P,     // [BATCH, T, 256] (biases included)
    const float* __restrict__ Whh,   // [256, 64]
    float* __restrict__ hout)        // WRITE_ALL ? [BATCH,T,64] : [BATCH,64]
{
    __shared__ __align__(16) float sH[4 * 64];
    __shared__ __align__(16) float sGate[4 * G];

    const int tid = threadIdx.x;
    const int b0  = blockIdx.x * 4;
    const int g   = tid;
    const int gt  = g >> 6;              // warp-uniform

    ull w[32];
    {
        const ull* wp = (const ull*)(Whh + g * 64);
        #pragma unroll
        for (int i = 0; i < 32; i++) w[i] = wp[i];
    }

    const int eb = tid >> 6;             // 0..3
    const int ej = tid & 63;
    float c = 0.0f;

    sH[tid] = 0.0f;

    const float* pbase = P + ((size_t)b0 * T) * G + g;
    float pc[4];
    #pragma unroll
    for (int b = 0; b < 4; b++) pc[b] = pbase[(size_t)b * T * G];
    __syncthreads();

    for (int t = 0; t < T; t++) {
        float pn[4];
        if (t + 1 < T) {
            #pragma unroll
            for (int b = 0; b < 4; b++)
                pn[b] = __ldcs(&pbase[(size_t)b * T * G + (size_t)(t + 1) * G]);
        }

        ull acc[4];
        #pragma unroll
        for (int b = 0; b < 4; b++) acc[b] = 0ull;

        #pragma unroll
        for (int kg = 0; kg < 16; kg++) {
            ull w01 = w[2 * kg], w23 = w[2 * kg + 1];
            #pragma unroll
            for (int b = 0; b < 4; b++) {
                ulonglong2 hv = *(const ulonglong2*)&sH[b * 64 + kg * 4];
                FMA2(acc[b], w01, hv.x);
                FMA2(acc[b], w23, hv.y);
            }
        }

        #pragma unroll
        for (int b = 0; b < 4; b++) {
            float lo, hi;
            UNPACK2(lo, hi, acc[b]);
            float v = lo + hi + pc[b];
            sGate[b * G + g] = (gt == 2) ? fast_tanh(v) : fast_sigmoid(v);
        }
        __syncthreads();

        {
            float iv = sGate[eb * G + ej];
            float fv = sGate[eb * G + 64 + ej];
            float gv = sGate[eb * G + 128 + ej];
            float ov = sGate[eb * G + 192 + ej];
            c = fmaf(fv, c, iv * gv);
            float h = ov * fast_tanh(c);
            sH[tid] = h;
            if (WRITE_ALL) {
                __stcs(&hout[(size_t)(b0 + eb) * T * HD + (size_t)t * HD + ej], h);
            } else if (t == T - 1) {
                hout[(b0 + eb) * HD + ej] = h;
            }
        }
        __syncthreads();

        #pragma unroll
        for (int b = 0; b < 4; b++) pc[b] = pn[b];
    }
}

// ---------------------------------------------------------------------------
// Decoder: 512 threads, BT=8. Half-split register weights.
// ---------------------------------------------------------------------------
__global__ void __launch_bounds__(512, 1) lstm_decoder(
    const float* __restrict__ Wih0, const float* __restrict__ bih0, const float* __restrict__ bhh0,
    const float* __restrict__ Wih1, const float* __restrict__ bih1, const float* __restrict__ bhh1,
    const float* __restrict__ Wfc,  const float* __restrict__ bfc,
    const float* __restrict__ h2last,
    float* __restrict__ out)   // [BATCH, PRED, 64]
{
    __shared__ __align__(16) ull   sWfcp[32 * 64];   // [kpair][j] packed (16 KB)
    __shared__ float sBfc[64];
    __shared__ __align__(16) float sIn[8 * 64];
    __shared__ __align__(16) float sHm[8 * 64];
    __shared__ __align__(16) float sGate[8 * G];

    const int tid  = threadIdx.x;
    const int b0   = blockIdx.x * 8;
    const int half = tid >> 8;           // 0: cell0 gates, 1: cell1 gates
    const int hg   = tid & 255;
    const int gt   = hg >> 6;
    const int eb   = tid >> 6;           // 0..7
    const int ej   = tid & 63;

    ull w[32];
    {
        const float* wsrc = half ? (Wih1 + hg * 64) : (Wih0 + hg * 64);
        const ull* wp = (const ull*)wsrc;
        #pragma unroll
        for (int i = 0; i < 32; i++) w[i] = wp[i];
    }
    const float bias = half ? (bih1[hg] + bhh1[hg]) : (bih0[hg] + bhh0[hg]);

    if (tid < 64) {
        const ull* wf = (const ull*)(Wfc + tid * 64);
        #pragma unroll
        for (int i = 0; i < 32; i++) sWfcp[i * 64 + tid] = wf[i];
        sBfc[tid] = bfc[tid];
    }
    sIn[tid] = h2last[b0 * 64 + tid];
    __syncthreads();

    for (int s = 0; s < PRED; s++) {
        // ---- cell0: lower half computes gates from sIn ----
        if (half == 0) {
            ull acc[8];
            #pragma unroll
            for (int b = 0; b < 8; b++) acc[b] = 0ull;
            #pragma unroll
            for (int kg = 0; kg < 16; kg++) {
                ull w01 = w[2 * kg], w23 = w[2 * kg + 1];
                #pragma unroll
                for (int b = 0; b < 8; b++) {
                    ulonglong2 xv = *(const ulonglong2*)&sIn[b * 64 + kg * 4];
                    FMA2(acc[b], w01, xv.x);
                    FMA2(acc[b], w23, xv.y);
                }
            }
            #pragma unroll
            for (int b = 0; b < 8; b++) {
                float lo, hi;
                UNPACK2(lo, hi, acc[b]);
                float v = lo + hi + bias;
                sGate[b * G + hg] = (gt == 2) ? fast_tanh(v) : fast_sigmoid(v);
            }
        }
        __syncthreads();
        {
            float iv = sGate[eb * G + ej];
            float gv = sGate[eb * G + 128 + ej];
            float ov = sGate[eb * G + 192 + ej];
            sHm[tid] = ov * fast_tanh(iv * gv);
        }
        __syncthreads();

        // ---- cell1: upper half computes gates from sHm ----
        if (half == 1) {
            ull acc[8];
            #pragma unroll
            for (int b = 0; b < 8; b++) acc[b] = 0ull;
            #pragma unroll
            for (int kg = 0; kg < 16; kg++) {
                ull w01 = w[2 * kg], w23 = w[2 * kg + 1];
                #pragma unroll
                for (int b = 0; b < 8; b++) {
                    ulonglong2 xv = *(const ulonglong2*)&sHm[b * 64 + kg * 4];
                    FMA2(acc[b], w01, xv.x);
                    FMA2(acc[b], w23, xv.y);
                }
            }
            #pragma unroll
            for (int b = 0; b < 8; b++) {
                float lo, hi;
                UNPACK2(lo, hi, acc[b]);
                float v = lo + hi + bias;
                sGate[b * G + hg] = (gt == 2) ? fast_tanh(v) : fast_sigmoid(v);
            }
        }
        __syncthreads();
        {
            float iv = sGate[eb * G + ej];
            float gv = sGate[eb * G + 128 + ej];
            float ov = sGate[eb * G + 192 + ej];
            sHm[tid] = ov * fast_tanh(iv * gv);
        }
        __syncthreads();

        // ---- FC: one output per thread (eb, ej) ----
        {
            ull acc = 0ull;
            #pragma unroll
            for (int i = 0; i < 16; i++) {
                ull w01 = sWfcp[(2 * i) * 64 + ej];
                ull w23 = sWfcp[(2 * i + 1) * 64 + ej];
                ulonglong2 xv = *(const ulonglong2*)&sHm[eb * 64 + i * 4];
                FMA2(acc, w01, xv.x);
                FMA2(acc, w23, xv.y);
            }
            float lo, hi;
            UNPACK2(lo, hi, acc);
            float pred = lo + hi + sBfc[ej];
            out[(size_t)(b0 + eb) * PRED * HD + (size_t)s * HD + ej] = pred;
            sIn[tid] = pred;
            __syncthreads();
        }
    }
}

// ---------------------------------------------------------------------------
extern "C" void kernel_launch(void* const* d_in, const int* in_sizes, int n_in,
                              void* d_out, int out_size)
{
    const float* x    = (const float*)d_in[0];
    const float* Wih0 = (const float*)d_in[1];
    const float* Whh0 = (const float*)d_in[2];
    const float* bih0 = (const float*)d_in[3];
    const float* bhh0 = (const float*)d_in[4];
    const float* Wih1 = (const float*)d_in[5];
    const float* Whh1 = (const float*)d_in[6];
    const float* bih1 = (const float*)d_in[7];
    const float* bhh1 = (const float*)d_in[8];
    const float* Wfc  = (const float*)d_in[9];
    const float* bfc  = (const float*)d_in[10];
    float* out = (float*)d_out;

    float *pbuf = nullptr, *h1 = nullptr, *h2l = nullptr;
    cudaGetSymbolAddress((void**)&pbuf, g_p);
    cudaGetSymbolAddress((void**)&h1,   g_h1);
    cudaGetSymbolAddress((void**)&h2l,  g_h2last);

    input_gemm<<<296, 256>>>(x, Wih0, bih0, bhh0, pbuf, NROWS);
    lstm_recur<true ><<<256, 256>>>(pbuf, Whh0, h1);

    input_gemm<<<296, 256>>>(h1, Wih1, bih1, bhh1, pbuf, NROWS);
    lstm_recur<false><<<256, 256>>>(pbuf, Whh1, h2l);

    lstm_decoder<<<128, 512>>>(Wih0, bih0, bhh0, Wih1, bih1, bhh1,
                               Wfc, bfc, h2l, out);
}